// round 15
// baseline (speedup 1.0000x reference)
#include <cuda_runtime.h>

// Problem constants (fixed for this registry problem instance)
#define BB 32
#define ZZ 384
#define NV 68
#define MC 46
#define DC 7
#define EE (MC*DC)          // 322
#define NG 4                // variables per phase1 item (68 = 17*4)
#define NGRP (NV/NG)        // 17
#define MAXD 8              // unrolled predicated edge batch in phase1
#define NBLK 148            // persistent grid: 1 block/SM -> co-residency GUARANTEED
#define P2_ITEMS (BB*MC)    // 1472
#define P1_ITEMS (BB*NGRP)  // 544
#define P2_SLOTS 10         // ceil(1472/148)
#define P1_SLOTS 4          // ceil(544/148)

// Device scratch (no cudaMalloc allowed)
__device__ float g_tot[BB*NV*ZZ];     // tot_plus = xa + sum(c2v), layout [b][n][z]
__device__ float g_xaT[BB*NV*ZZ];     // transposed xa, layout [b][n][z]
// c2v stored as int8 = 2*value (exact half-integers in [-7.5,7.5]),
// in VARIABLE z-domain: c2v_v[b][e][zv], zv=(zm+shift_e)%Z.
__device__ signed char g_c2v8[BB*EE*ZZ];
__device__ int   g_inv_off[NV+1];     // CSR: variable -> its edges
__device__ int   g_inv_eoff[EE];      // per edge (var-sorted): e*ZZ (byte offset)
// grid-barrier state (reset each launch by k_build_inv)
__device__ unsigned          g_bar_count;
__device__ volatile unsigned g_bar_seq;

// ---------------------------------------------------------------------------
// Init: tiled transpose xa[b][z][n] -> g_xaT/g_tot [b][n][z].
// ---------------------------------------------------------------------------
__global__ void k_init(const float* __restrict__ xa) {
    __shared__ float tile[32][33];
    int bid = blockIdx.x;
    int nt = bid % 3;                 // n-tile (0..2, covers 96 >= 68)
    int zt = (bid / 3) % (ZZ/32);     // z-tile
    int b  = bid / (3 * (ZZ/32));
    int n0 = nt * 32, z0 = zt * 32;
    int tx = threadIdx.x, ty = threadIdx.y;

    int n = n0 + tx;
#pragma unroll
    for (int r = 0; r < 4; r++) {
        int z = z0 + ty + r*8;
        if (n < NV) tile[ty + r*8][tx] = xa[(b*ZZ + z)*NV + n];
    }
    __syncthreads();
#pragma unroll
    for (int r = 0; r < 4; r++) {
        int nn = n0 + ty + r*8;
        int zz = z0 + tx;
        if (nn < NV) {
            float v = tile[tx][ty + r*8];
            int idx = (b*NV + nn)*ZZ + zz;
            g_xaT[idx] = v;
            g_tot[idx] = v;          // iteration 0: c2v = 0 -> tot_plus = xa
        }
    }
}

// ---------------------------------------------------------------------------
// Build inverse index + reset barrier state (runs before the fused kernel
// every launch -> graph replay safe).
// ---------------------------------------------------------------------------
__global__ void k_build_inv(const int* __restrict__ vn) {
    __shared__ int off[NV+1];
    __shared__ int cur[NV];
    int t = threadIdx.x;
    if (t == 0) { g_bar_count = 0u; g_bar_seq = 0u; }
    for (int i = t; i <= NV; i += blockDim.x) off[i] = 0;
    __syncthreads();
    for (int e = t; e < EE; e += blockDim.x) atomicAdd(&off[vn[e] + 1], 1);
    __syncthreads();
    if (t == 0) {
        int s = 0;
        for (int i = 0; i <= NV; i++) { s += off[i]; off[i] = s; }
    }
    __syncthreads();
    for (int i = t; i <= NV; i += blockDim.x) g_inv_off[i] = off[i];
    for (int i = t; i <  NV; i += blockDim.x) cur[i] = off[i];
    __syncthreads();
    for (int e = t; e < EE; e += blockDim.x) {
        int p = atomicAdd(&cur[vn[e]], 1);
        g_inv_eoff[p] = e * ZZ;
    }
}

// ---------------------------------------------------------------------------
// Grid barrier: monotonic arrival count + volatile release sequence.
// __threadfence() before arrival publishes writes; __threadfence() after
// release is gpu-scope (CCTL.IVALL on sm_103a) -> no stale L1 lines after.
// NBLK=148 = one block per SM: a single 384-thread block always fits
// (<=170 regs enforced by launch bounds, ~2KB smem), and a 148-block grid
// is entirely wave-1 resident -> the barrier cannot starve. (The R13/R14
// hang: at NBLK=296, regs>85 silently dropped residency to 1 block/SM and
// half the grid never launched.)
// ---------------------------------------------------------------------------
__device__ __forceinline__ void grid_barrier(unsigned phase) {
    __syncthreads();
    if (threadIdx.x == 0) {
        __threadfence();
        unsigned prev = atomicAdd(&g_bar_count, 1u);
        if (prev == phase * NBLK - 1u) {
            g_bar_seq = phase;                 // release
        } else {
            while (g_bar_seq < phase) __nanosleep(64);
        }
    }
    __syncthreads();
    __threadfence();                           // acquire + L1 invalidate
}

// ---------------------------------------------------------------------------
// Fused persistent decoder: all 8 iterations (phase2 + phase1) in ONE launch.
// Item tables (check vn/sh, variable CSR edges) staged in smem once and
// reused across iterations. Math identical to the committed R11 kernels:
// bit-exact (int8 c2v = 2*value, exact integer sums, single rounded add,
// rintf round-half-even, min1/min2/first-argmin tie-break).
// ---------------------------------------------------------------------------
__global__ void __launch_bounds__(ZZ) k_fused(
    const int* __restrict__ vn, const int* __restrict__ sh,
    const float* __restrict__ cw, int iters, float* __restrict__ dst) {
    int tid = threadIdx.x;
    int bid = blockIdx.x;

    // ---- stage per-item tables once ----
    __shared__ int s2n[P2_SLOTS][DC], s2s[P2_SLOTS][DC];   // phase2: vars, shifts
    __shared__ int s2bc[P2_SLOTS][2];                      // phase2: (b, c)
    __shared__ int s1eo[P1_SLOTS][NG][16];                 // phase1: edge offsets
    __shared__ int s1deg[P1_SLOTS][NG];                    // phase1: degrees
    __shared__ int s1bn[P1_SLOTS][2];                      // phase1: (b, n0)

    {
        int slot = 0;
        for (int item = bid; item < P2_ITEMS; item += NBLK, ++slot) {
            int c = item % MC;
            if (tid < DC) {
                s2n[slot][tid] = vn[c*DC + tid];
                s2s[slot][tid] = sh[c*DC + tid];
            }
            if (tid == 0) { s2bc[slot][0] = item / MC; s2bc[slot][1] = c; }
        }
        for (; slot < P2_SLOTS; ++slot) if (tid == 0) s2bc[slot][0] = -1;

        slot = 0;
        for (int item = bid; item < P1_ITEMS; item += NBLK, ++slot) {
            int n0 = (item % NGRP) * NG;
            if (tid < NG*16) {
                int nn = tid / 16, k = tid % 16;
                int k0 = g_inv_off[n0 + nn], k1 = g_inv_off[n0 + nn + 1];
                if (k == 0) s1deg[slot][nn] = k1 - k0;
                if (k < k1 - k0) s1eo[slot][nn][k] = g_inv_eoff[k0 + k];
            }
            if (tid == 0) { s1bn[slot][0] = item / NGRP; s1bn[slot][1] = n0; }
        }
        for (; slot < P1_SLOTS; ++slot) if (tid == 0) s1bn[slot][0] = -1;
    }
    __syncthreads();

    int nn = tid / (ZZ/4);               // phase1: 0..3, uniform per warp
    int z4 = (tid % (ZZ/4)) * 4;         // phase1: byte/z offset of 4 z's

    unsigned bar = 1u;
    for (int it = 0; it < iters; ++it) {
        int first = (it == 0);
        float w = __ldg(cw + it);

        // ================= phase 2: check-node min-sum =================
#pragma unroll 1
        for (int slot = 0; slot < P2_SLOTS; ++slot) {
            int b = s2bc[slot][0];
            if (b < 0) break;
            int c = s2bc[slot][1];
            int zm = tid;
            const float* totb = g_tot + b*NV*ZZ;
            signed char* cvb  = g_c2v8 + (b*EE + c*DC)*ZZ;

            int zv[DC];
#pragma unroll
            for (int j = 0; j < DC; j++) {
                int t2 = zm + s2s[slot][j]; if (t2 >= ZZ) t2 -= ZZ;
                zv[j] = t2;
            }
            float tp[DC];
            int   oldq[DC];
#pragma unroll
            for (int j = 0; j < DC; j++) tp[j] = totb[s2n[slot][j]*ZZ + zv[j]];
#pragma unroll
            for (int j = 0; j < DC; j++) oldq[j] = first ? 0 : (int)cvb[j*ZZ + zv[j]];

            float mn1 = 1e30f, mn2 = 1e30f;
            int arg = 0;
            unsigned sb = 0;
#pragma unroll
            for (int j = 0; j < DC; j++) {
                float x = tp[j] - (float)oldq[j] * 0.5f;  // exact half-integer
                x = fminf(fmaxf(x, -20.0f), 20.0f);
                if (x < 0.0f) sb |= (1u << j);
                float a = fabsf(x);
                if (a < mn1) { mn2 = mn1; mn1 = a; arg = j; }
                else         { mn2 = fminf(mn2, a); }
            }
            int par = __popc(sb) & 1;
            // clip(round(2*w*min), +-15); rintf = round-half-even = jnp.round
            int iq1 = (int)fminf(fmaxf(rintf(2.0f * (w * mn1)), -15.0f), 15.0f);
            int iq2 = (int)fminf(fmaxf(rintf(2.0f * (w * mn2)), -15.0f), 15.0f);
#pragma unroll
            for (int j = 0; j < DC; j++) {
                int q = (j == arg) ? iq2 : iq1;
                int neg = (par ^ (int)(sb >> j)) & 1;     // extrinsic sign
                cvb[j*ZZ + zv[j]] = (signed char)(neg ? -q : q);
            }
        }

        grid_barrier(bar++);

        // ================= phase 1: variable-node sum ==================
        float* outp = (it == iters-1) ? dst : g_tot;
#pragma unroll 1
        for (int slot = 0; slot < P1_SLOTS; ++slot) {
            int b = s1bn[slot][0];
            if (b < 0) break;
            int n = s1bn[slot][1] + nn;
            int deg = s1deg[slot][nn];
            const signed char* cvb = g_c2v8 + b*EE*ZZ + z4;

            int eo[MAXD];
#pragma unroll
            for (int k = 0; k < MAXD; k++) eo[k] = s1eo[slot][nn][k];
            int v[MAXD];
#pragma unroll
            for (int k = 0; k < MAXD; k++)
                v[k] = (k < deg) ? *(const int*)(cvb + eo[k]) : 0;

            int a0 = 0, a1 = 0, a2 = 0, a3 = 0;
#pragma unroll
            for (int k = 0; k < MAXD; k++) {
                a0 += (v[k] << 24) >> 24;
                a1 += (v[k] << 16) >> 24;
                a2 += (v[k] <<  8) >> 24;
                a3 +=  v[k]        >> 24;
            }
            for (int k = MAXD; k < deg; k++) {            // rare high degree
                int vv = *(const int*)(cvb + s1eo[slot][nn][k]);
                a0 += (vv << 24) >> 24;
                a1 += (vv << 16) >> 24;
                a2 += (vv <<  8) >> 24;
                a3 +=  vv        >> 24;
            }

            int idx = (b*NV + n)*ZZ + z4;
            float4 xa4 = *(const float4*)(g_xaT + idx);
            float4 o;
            o.x = fmaf((float)a0, 0.5f, xa4.x);   // sum*0.5 exact; one rounded add
            o.y = fmaf((float)a1, 0.5f, xa4.y);
            o.z = fmaf((float)a2, 0.5f, xa4.z);
            o.w = fmaf((float)a3, 0.5f, xa4.w);
            *(float4*)(outp + idx) = o;           // out[b, n*Z+z] == [b][n][z]
        }

        if (it != iters-1) grid_barrier(bar++);
    }
}

// ---------------------------------------------------------------------------
extern "C" void kernel_launch(void* const* d_in, const int* in_sizes, int n_in,
                              void* d_out, int out_size) {
    const float* xa = (const float*)d_in[0];
    const float* cw = (const float*)d_in[1];
    const int*   vn = (const int*)d_in[2];
    // d_in[3] = cn_idx: structure is repeat(arange(M), dc) -> implicit (e/7)
    const int*   sh = (const int*)d_in[4];

    int iters = in_sizes[1];   // cn_weights length = 8

    k_init<<<BB * (ZZ/32) * 3, dim3(32, 8)>>>(xa);
    k_build_inv<<<1, 256>>>(vn);
    k_fused<<<NBLK, ZZ>>>(vn, sh, cw, iters, (float*)d_out);
}